// round 4
// baseline (speedup 1.0000x reference)
#include <cuda_runtime.h>
#include <math.h>

#define B_N   8192
#define DIN   256
#define DE    128
#define NEX   16384
#define NDUR  64
#define GAMMA_N 3.6787944117144233e-06f   // exp(-1)/100000

typedef unsigned long long u64;

// ---------------- device scratch ----------------
__device__ __align__(16) float g_phi[B_N * DE];      // -2*phi, [B][DE]
__device__ __align__(16) float g_pn[B_N];            // ||phi||^2
__device__ __align__(16) float g_en[NEX];            // ||E||^2
__device__ __align__(16) float g_KMT[NDUR * NEX];    // exemplar KM transposed [d][NEX]
__device__ __align__(16) float g_gbh[NDUR];          // gamma * baseline KM
__device__ __align__(16) float g_pnum[2 * B_N * NDUR];
__device__ __align__(16) float g_pden[2 * B_N];

// ---------------- helpers ----------------
__device__ __forceinline__ void cp_async16(void* smem, const void* gmem) {
    unsigned sa = (unsigned)__cvta_generic_to_shared(smem);
    asm volatile("cp.async.cg.shared.global [%0], [%1], 16;" :: "r"(sa), "l"(gmem));
}
#define CP_COMMIT() asm volatile("cp.async.commit_group;" ::: "memory")
#define CP_WAIT1()  asm volatile("cp.async.wait_group 1;" ::: "memory")
#define CP_WAIT0()  asm volatile("cp.async.wait_group 0;" ::: "memory")

__device__ __forceinline__ void ffma2(u64 &d, u64 a, u64 b) {
    asm("fma.rn.f32x2 %0, %1, %2, %0;" : "+l"(d) : "l"(a), "l"(b));
}
__device__ __forceinline__ float upsum(u64 v) {
    float lo, hi;
    asm("mov.b64 {%0, %1}, %2;" : "=f"(lo), "=f"(hi) : "l"(v));
    return lo + hi;
}

// ---------------- kernel 1: g_phi = -2*(x@W + b) [B][DE], g_pn = ||phi||^2 ----
// 512 blocks x 128 threads, 16 rows/block; thread j owns embedding dim j
__global__ void phi_pn_kernel(const float* __restrict__ x,
                              const float* __restrict__ W,
                              const float* __restrict__ bias) {
    __shared__ float xs[16 * DIN];
    __shared__ float pnred[16][4];
    const int tid = threadIdx.x;
    const int r0 = blockIdx.x * 16;

    const float4* xv = reinterpret_cast<const float4*>(x + r0 * DIN);
    float4* xsv = reinterpret_cast<float4*>(xs);
    #pragma unroll
    for (int i = 0; i < 8; ++i) xsv[tid + i * 128] = xv[tid + i * 128];
    const float bj = bias[tid];
    __syncthreads();

    float a[16];
    #pragma unroll
    for (int r = 0; r < 16; ++r) a[r] = 0.f;
    #pragma unroll 4
    for (int k = 0; k < DIN; ++k) {
        float w = W[k * DE + tid];
        #pragma unroll
        for (int r = 0; r < 16; ++r) a[r] += xs[r * DIN + k] * w;
    }
    #pragma unroll
    for (int r = 0; r < 16; ++r) {
        float v = a[r] + bj;
        g_phi[(r0 + r) * DE + tid] = -2.f * v;
        a[r] = v * v;
    }
    const int lane = tid & 31, warp = tid >> 5;
    #pragma unroll
    for (int r = 0; r < 16; ++r) {
        float v = a[r];
        #pragma unroll
        for (int o = 16; o; o >>= 1) v += __shfl_xor_sync(0xffffffffu, v, o);
        if (lane == 0) pnred[r][warp] = v;
    }
    __syncthreads();
    if (tid < 16)
        g_pn[r0 + tid] = pnred[tid][0] + pnred[tid][1] + pnred[tid][2] + pnred[tid][3];
}

// ---------------- kernel 2: en[n] = ||E_n||^2 ----------------
__global__ void en_kernel(const float* __restrict__ E) {
    const int warp = threadIdx.x >> 5, lane = threadIdx.x & 31;
    const int row = blockIdx.x * 8 + warp;
    const float4* Ev = reinterpret_cast<const float4*>(E);
    float4 v = Ev[row * (DE / 4) + lane];
    float s = v.x * v.x + v.y * v.y + v.z * v.z + v.w * v.w;
    #pragma unroll
    for (int o = 16; o; o >>= 1) s += __shfl_xor_sync(0xffffffffu, s, o);
    if (lane == 0) g_en[row] = s;
}

// ---------------- kernel 3: exemplar KM curves -> g_KMT [d][NEX] ----------------
__global__ void km_kernel(const float* __restrict__ lev,
                          const float* __restrict__ lcen) {
    __shared__ float buf[4][64];
    const int t = threadIdx.x, ty = threadIdx.y;
    const int row = blockIdx.x * 4 + ty;
    float ev = expf(lev[row * NDUR + t]);
    float cn = expf(lcen[row * NDUR + t]);
    float v = ev + cn;
    buf[ty][t] = v;
    #pragma unroll
    for (int off = 1; off < 64; off <<= 1) {
        __syncthreads();
        float add = (t + off < 64) ? buf[ty][t + off] : 0.f;
        __syncthreads();
        v += add;
        buf[ty][t] = v;
    }
    float at_risk = v;
    float hz = (at_risk > 0.f) ? (ev / at_risk) : 0.f;
    float lg = logf(1.f - hz + 1e-7f);
    __syncthreads();
    buf[ty][t] = lg;
    float c = lg;
    #pragma unroll
    for (int off = 1; off < 64; off <<= 1) {
        __syncthreads();
        float add = (t >= off) ? buf[ty][t - off] : 0.f;
        __syncthreads();
        c += add;
        buf[ty][t] = c;
    }
    g_KMT[t * NEX + row] = expf(c);   // transposed store
}

// ---------------- kernel 4: gamma * baseline KM ----------------
__global__ void bh_kernel(const float* __restrict__ lh) {
    if (threadIdx.x == 0 && blockIdx.x == 0) {
        float c = 0.f;
        for (int tt = 0; tt < NDUR; ++tt) {
            float h = 1.f / (1.f + expf(-lh[tt]));
            c += logf(1.f - h + 1e-7f);
            g_gbh[tt] = GAMMA_N * expf(c);
        }
    }
}

// ---------------- kernel 5: fused main (f32x2-packed) ----------------
// grid (64, 2): x = 128-row B tile, y = NE half. 256 threads.
// mG=tid>>4 (m0=mG*8), lG=tid&15 (n0=lG*4, d0=lG*4)
// smem layouts (all XOR-swizzled at 16B-chunk granularity):
//   As   [m][k]  128x128  chunk(m,kg) at quad kg ^ ((m>>2)&31)
//   Bs   [n][k]  2x64x128 chunk(n,kg) at quad kg ^ (n>>2)
//   kws  [m][n]  128x64   chunk(m,ng) at quad ng ^ ((m>>2)&15)
//   KMs_T[d][n]  64x64    chunk(d,ng) at quad ng ^ ((d>>2)&15)
#define TILE_N 64
#define SM_AS   0        // 16384 floats
#define SM_BS   16384    // 2*8192 floats
#define SM_KWS  32768    // 8192 floats
#define SM_KMS  40960    // 4096 floats
#define SM_ENS  45056    // 64 floats
#define SM_RED  45120    // 2048 floats
#define SM_FLOATS 47168

__device__ __forceinline__ void issue_E(float* Bsbuf, const float* __restrict__ E,
                                        int nb, int tid) {
    #pragma unroll
    for (int i = 0; i < 8; ++i) {
        int f = tid + i * 256;
        int n = f >> 5, kg = f & 31;
        int q = (kg ^ (n >> 2)) & 31;
        cp_async16(Bsbuf + n * 128 + q * 4, E + (nb + n) * DE + kg * 4);
    }
}
__device__ __forceinline__ void issue_KM(float* kms, float* ens, int nb, int tid) {
    #pragma unroll
    for (int i = 0; i < 4; ++i) {
        int f = tid + i * 256;
        int d = f >> 4, ng = f & 15;
        int q = (ng ^ ((d >> 2) & 15)) & 15;
        cp_async16(kms + d * 64 + q * 4, g_KMT + d * NEX + nb + ng * 4);
    }
    if (tid < 16) cp_async16(ens + tid * 4, g_en + nb + tid * 4);
}

extern "C" __global__ void __launch_bounds__(256, 1)
main_kernel(const float* __restrict__ E) {
    extern __shared__ float sm[];
    float* As  = sm + SM_AS;
    float* Bs  = sm + SM_BS;
    float* kws = sm + SM_KWS;
    float* KMs = sm + SM_KMS;
    float* ens = sm + SM_ENS;
    float* red = sm + SM_RED;

    const int tid = threadIdx.x;
    const int bm = blockIdx.x;
    const int split = blockIdx.y;
    const int mG = tid >> 4, lG = tid & 15;
    const int m0 = mG * 8, n0 = lG * 4, d0 = lG * 4;
    const int nsplit0 = split * (NEX / 2);

    issue_E(Bs, E, nsplit0, tid);
    CP_COMMIT();

    // As tile: g_phi rows, swizzled
    #pragma unroll
    for (int i = 0; i < 16; ++i) {
        int f = tid + i * 256;
        int m = f >> 5, kg = f & 31;
        float4 v = *reinterpret_cast<const float4*>(g_phi + (bm * 128 + m) * DE + kg * 4);
        int q = (kg ^ ((m >> 2) & 31)) & 31;
        *reinterpret_cast<float4*>(As + m * 128 + q * 4) = v;
    }
    float pnr[8];
    #pragma unroll
    for (int i = 0; i < 8; ++i) pnr[i] = g_pn[bm * 128 + m0 + i];

    u64 acc2p[8][4];
    #pragma unroll
    for (int mi = 0; mi < 8; ++mi)
        #pragma unroll
        for (int di = 0; di < 4; ++di) acc2p[mi][di] = 0ull;
    float denomAcc[8];
    #pragma unroll
    for (int mi = 0; mi < 8; ++mi) denomAcc[mi] = 0.f;

    int cur = 0;
    for (int t = 0; t < 128; ++t) {
        const int nb = nsplit0 + t * TILE_N;
        __syncthreads();   // protect KMs/kws/Bs reuse

        issue_KM(KMs, ens, nb, tid);
        CP_COMMIT();
        if (t + 1 < 128) {
            issue_E(Bs + (cur ^ 1) * (TILE_N * DE), E, nb + TILE_N, tid);
            CP_COMMIT();
            CP_WAIT1();
        } else {
            CP_WAIT0();
        }
        __syncthreads();

        const float* BsCur = Bs + cur * (TILE_N * DE);

        // ---- GEMM1: k-packed f32x2 ----
        u64 acc1p[8][4];
        #pragma unroll
        for (int mi = 0; mi < 8; ++mi)
            #pragma unroll
            for (int ni = 0; ni < 4; ++ni) acc1p[mi][ni] = 0ull;

        #pragma unroll 8
        for (int kq = 0; kq < 32; ++kq) {
            const int qa0 = (kq ^ (mG * 2)) & 31;
            const int qa1 = qa0 ^ 1;
            const int qb = (kq ^ lG) & 31;
            ulonglong2 b0 = *reinterpret_cast<const ulonglong2*>(BsCur + (n0 + 0) * 128 + qb * 4);
            ulonglong2 b1 = *reinterpret_cast<const ulonglong2*>(BsCur + (n0 + 1) * 128 + qb * 4);
            ulonglong2 b2 = *reinterpret_cast<const ulonglong2*>(BsCur + (n0 + 2) * 128 + qb * 4);
            ulonglong2 b3 = *reinterpret_cast<const ulonglong2*>(BsCur + (n0 + 3) * 128 + qb * 4);
            #pragma unroll
            for (int mi = 0; mi < 8; ++mi) {
                const int q = (mi < 4) ? qa0 : qa1;
                ulonglong2 a = *reinterpret_cast<const ulonglong2*>(As + (m0 + mi) * 128 + q * 4);
                ffma2(acc1p[mi][0], a.x, b0.x); ffma2(acc1p[mi][0], a.y, b0.y);
                ffma2(acc1p[mi][1], a.x, b1.x); ffma2(acc1p[mi][1], a.y, b1.y);
                ffma2(acc1p[mi][2], a.x, b2.x); ffma2(acc1p[mi][2], a.y, b2.y);
                ffma2(acc1p[mi][3], a.x, b3.x); ffma2(acc1p[mi][3], a.y, b3.y);
            }
        }

        // ---- epilogue: kw = mask * exp(-d2) ----
        float4 env = *reinterpret_cast<const float4*>(ens + n0);
        const float en4[4] = {env.x, env.y, env.z, env.w};
        #pragma unroll
        for (int mi = 0; mi < 8; ++mi) {
            float4 kv;
            float* kvp = reinterpret_cast<float*>(&kv);
            #pragma unroll
            for (int ni = 0; ni < 4; ++ni) {
                float d2 = pnr[mi] + en4[ni] + upsum(acc1p[mi][ni]);
                d2 = fmaxf(d2, 0.f);
                float kw = (d2 <= 1.0f) ? __expf(-d2) : 0.f;
                denomAcc[mi] += kw;
                kvp[ni] = kw;
            }
            const int q = (lG ^ (((m0 + mi) >> 2) & 15)) & 15;
            *reinterpret_cast<float4*>(kws + (m0 + mi) * 64 + q * 4) = kv;
        }
        __syncthreads();

        // ---- GEMM2: n-packed f32x2 ----
        #pragma unroll 4
        for (int nq = 0; nq < 16; ++nq) {
            const int qm0 = (nq ^ ((mG * 2) & 15)) & 15;
            const int qm1 = qm0 ^ 1;
            const int qk = (nq ^ lG) & 15;
            ulonglong2 k0 = *reinterpret_cast<const ulonglong2*>(KMs + (d0 + 0) * 64 + qk * 4);
            ulonglong2 k1 = *reinterpret_cast<const ulonglong2*>(KMs + (d0 + 1) * 64 + qk * 4);
            ulonglong2 k2 = *reinterpret_cast<const ulonglong2*>(KMs + (d0 + 2) * 64 + qk * 4);
            ulonglong2 k3 = *reinterpret_cast<const ulonglong2*>(KMs + (d0 + 3) * 64 + qk * 4);
            #pragma unroll
            for (int mi = 0; mi < 8; ++mi) {
                const int q = (mi < 4) ? qm0 : qm1;
                ulonglong2 w = *reinterpret_cast<const ulonglong2*>(kws + (m0 + mi) * 64 + q * 4);
                ffma2(acc2p[mi][0], w.x, k0.x); ffma2(acc2p[mi][0], w.y, k0.y);
                ffma2(acc2p[mi][1], w.x, k1.x); ffma2(acc2p[mi][1], w.y, k1.y);
                ffma2(acc2p[mi][2], w.x, k2.x); ffma2(acc2p[mi][2], w.y, k2.y);
                ffma2(acc2p[mi][3], w.x, k3.x); ffma2(acc2p[mi][3], w.y, k3.y);
            }
        }
        cur ^= 1;
    }

    // write partial numerators
    #pragma unroll
    for (int mi = 0; mi < 8; ++mi) {
        float4 o = make_float4(upsum(acc2p[mi][0]), upsum(acc2p[mi][1]),
                               upsum(acc2p[mi][2]), upsum(acc2p[mi][3]));
        *reinterpret_cast<float4*>(
            &g_pnum[(split * B_N + bm * 128 + m0 + mi) * NDUR + d0]) = o;
    }

    // denom reduction across 16 lG groups
    __syncthreads();
    #pragma unroll
    for (int mi = 0; mi < 8; ++mi) red[lG * 128 + m0 + mi] = denomAcc[mi];
    __syncthreads();
    if (tid < 128) {
        float s = 0.f;
        #pragma unroll
        for (int g = 0; g < 16; ++g) s += red[g * 128 + tid];
        g_pden[split * B_N + bm * 128 + tid] = s;
    }
}

// ---------------- kernel 6: finalize ----------------
__global__ void finalize_kernel(float* __restrict__ out) {
    const int idx = blockIdx.x * 256 + threadIdx.x;
    const int b = idx >> 6, d = idx & 63;
    float num = g_pnum[idx] + g_pnum[B_N * NDUR + idx] + g_gbh[d];
    float den = g_pden[b] + g_pden[B_N + b] + GAMMA_N + 1e-12f;
    float r = num / den;
    r = fminf(fmaxf(r, 1e-12f), 1.0f - 1e-12f);
    out[idx] = r;
}

// ---------------- launch ----------------
extern "C" void kernel_launch(void* const* d_in, const int* in_sizes, int n_in,
                              void* d_out, int out_size) {
    const float* x    = (const float*)d_in[0];
    const float* W    = (const float*)d_in[1];
    const float* bias = (const float*)d_in[2];
    const float* E    = (const float*)d_in[3];
    const float* lev  = (const float*)d_in[4];
    const float* lcen = (const float*)d_in[5];
    const float* lh   = (const float*)d_in[6];
    float* out = (float*)d_out;

    static bool attr_set = false;
    if (!attr_set) {
        cudaFuncSetAttribute(main_kernel,
                             cudaFuncAttributeMaxDynamicSharedMemorySize,
                             SM_FLOATS * sizeof(float));
        attr_set = true;
    }

    phi_pn_kernel<<<B_N / 16, 128>>>(x, W, bias);
    en_kernel<<<NEX / 8, 256>>>(E);
    km_kernel<<<NEX / 4, dim3(64, 4)>>>(lev, lcen);
    bh_kernel<<<1, 32>>>(lh);
    main_kernel<<<dim3(B_N / 128, 2), 256, SM_FLOATS * sizeof(float)>>>(E);
    finalize_kernel<<<(B_N * NDUR) / 256, 256>>>(out);
}

// round 7
// speedup vs baseline: 4.6127x; 4.6127x over previous
#include <cuda_runtime.h>
#include <cuda_bf16.h>
#include <math.h>
#include <stdint.h>

#define B_N   8192
#define DIN   256
#define DE    128
#define NEX   16384
#define NDUR  64
#define GAMMA_N 3.6787944117144233e-06f   // exp(-1)/100000

// ---------------- device scratch ----------------
__device__ __align__(16) __nv_bfloat16 g_phiB[B_N * DE];   // bf16(-2*phi) [B][128]
__device__ __align__(16) __nv_bfloat16 g_EB[NEX * DE];     // bf16(E)      [NEX][128]
__device__ __align__(16) __nv_bfloat16 g_KMTB[NDUR * NEX]; // bf16(KM^T)   [64][NEX]
__device__ __align__(16) float g_pn[B_N];                  // ||phi||^2
__device__ __align__(16) float g_en[NEX];                  // ||E||^2
__device__ __align__(16) float g_gbh[NDUR];                // gamma * baseline KM
__device__ __align__(16) float g_pnum[2 * B_N * NDUR];
__device__ __align__(16) float g_pden[2 * B_N];

// ---------------- helpers ----------------
__device__ __forceinline__ void cp_async16(void* smem, const void* gmem) {
    unsigned sa = (unsigned)__cvta_generic_to_shared(smem);
    asm volatile("cp.async.cg.shared.global [%0], [%1], 16;" :: "r"(sa), "l"(gmem));
}
#define CP_COMMIT() asm volatile("cp.async.commit_group;" ::: "memory")
#define CP_WAIT0()  asm volatile("cp.async.wait_group 0;" ::: "memory")

__device__ __forceinline__ void mma_bf16(float& c0, float& c1, float& c2, float& c3,
                                         uint32_t a0, uint32_t a1, uint32_t a2, uint32_t a3,
                                         uint32_t b0, uint32_t b1) {
    asm volatile(
        "mma.sync.aligned.m16n8k16.row.col.f32.bf16.bf16.f32 "
        "{%0,%1,%2,%3}, {%4,%5,%6,%7}, {%8,%9}, {%0,%1,%2,%3};"
        : "+f"(c0), "+f"(c1), "+f"(c2), "+f"(c3)
        : "r"(a0), "r"(a1), "r"(a2), "r"(a3), "r"(b0), "r"(b1));
}
__device__ __forceinline__ uint32_t pack_bf16x2(float lo, float hi) {
    uint32_t r;
    asm("cvt.rn.bf16x2.f32 %0, %1, %2;" : "=r"(r) : "f"(hi), "f"(lo));
    return r;
}

// ---------------- kernel 1: phi encoder -> g_phiB (bf16 -2phi), g_pn ----------------
// grid B_N/16, 128 threads; thread j owns embedding dim j
__global__ void phi_pn_kernel(const float* __restrict__ x,
                              const float* __restrict__ W,
                              const float* __restrict__ bias) {
    __shared__ float xs[16 * DIN];
    __shared__ float pnred[16][4];
    const int tid = threadIdx.x;
    const int r0 = blockIdx.x * 16;

    const float4* xv = reinterpret_cast<const float4*>(x + r0 * DIN);
    float4* xsv = reinterpret_cast<float4*>(xs);
    #pragma unroll
    for (int i = 0; i < 8; ++i) xsv[tid + i * 128] = xv[tid + i * 128];
    const float bj = bias[tid];
    __syncthreads();

    float a[16];
    #pragma unroll
    for (int r = 0; r < 16; ++r) a[r] = 0.f;
    #pragma unroll 4
    for (int k = 0; k < DIN; ++k) {
        float w = W[k * DE + tid];
        #pragma unroll
        for (int r = 0; r < 16; ++r) a[r] += xs[r * DIN + k] * w;
    }
    #pragma unroll
    for (int r = 0; r < 16; ++r) {
        float v = a[r] + bj;
        g_phiB[(r0 + r) * DE + tid] = __float2bfloat16(-2.f * v);
        a[r] = v * v;
    }
    const int lane = tid & 31, warp = tid >> 5;
    #pragma unroll
    for (int r = 0; r < 16; ++r) {
        float v = a[r];
        #pragma unroll
        for (int o = 16; o; o >>= 1) v += __shfl_xor_sync(0xffffffffu, v, o);
        if (lane == 0) pnred[r][warp] = v;
    }
    __syncthreads();
    if (tid < 16)
        g_pn[r0 + tid] = pnred[tid][0] + pnred[tid][1] + pnred[tid][2] + pnred[tid][3];
}

// ---------------- kernel 2: en[n] = ||E_n||^2 and g_EB = bf16(E) ----------------
__global__ void en_eb_kernel(const float* __restrict__ E) {
    const int warp = threadIdx.x >> 5, lane = threadIdx.x & 31;
    const int row = blockIdx.x * 8 + warp;
    const float4* Ev = reinterpret_cast<const float4*>(E);
    float4 v = Ev[row * (DE / 4) + lane];
    // bf16 conversion (4 elems -> 8 bytes)
    uint2 pk;
    pk.x = pack_bf16x2(v.x, v.y);
    pk.y = pack_bf16x2(v.z, v.w);
    *reinterpret_cast<uint2*>(reinterpret_cast<char*>(g_EB) + row * 256 + lane * 8) = pk;
    float s = v.x * v.x + v.y * v.y + v.z * v.z + v.w * v.w;
    #pragma unroll
    for (int o = 16; o; o >>= 1) s += __shfl_xor_sync(0xffffffffu, s, o);
    if (lane == 0) g_en[row] = s;
}

// ---------------- kernel 3: KM curves -> g_KMTB bf16 [d][NEX] ----------------
__global__ void km_kernel(const float* __restrict__ lev,
                          const float* __restrict__ lcen) {
    __shared__ float buf[4][64];
    const int t = threadIdx.x, ty = threadIdx.y;
    const int row = blockIdx.x * 4 + ty;
    float ev = expf(lev[row * NDUR + t]);
    float cn = expf(lcen[row * NDUR + t]);
    float v = ev + cn;
    buf[ty][t] = v;
    #pragma unroll
    for (int off = 1; off < 64; off <<= 1) {
        __syncthreads();
        float add = (t + off < 64) ? buf[ty][t + off] : 0.f;
        __syncthreads();
        v += add;
        buf[ty][t] = v;
    }
    float at_risk = v;
    float hz = (at_risk > 0.f) ? (ev / at_risk) : 0.f;
    float lg = logf(1.f - hz + 1e-7f);
    __syncthreads();
    buf[ty][t] = lg;
    float c = lg;
    #pragma unroll
    for (int off = 1; off < 64; off <<= 1) {
        __syncthreads();
        float add = (t >= off) ? buf[ty][t - off] : 0.f;
        __syncthreads();
        c += add;
        buf[ty][t] = c;
    }
    g_KMTB[t * NEX + row] = __float2bfloat16(expf(c));
}

// ---------------- kernel 4: gamma * baseline KM ----------------
__global__ void bh_kernel(const float* __restrict__ lh) {
    __shared__ float buf[64];
    const int t = threadIdx.x;
    float h = 1.f / (1.f + expf(-lh[t]));
    float c = logf(1.f - h + 1e-7f);
    buf[t] = c;
    #pragma unroll
    for (int off = 1; off < 64; off <<= 1) {
        __syncthreads();
        float add = (t >= off) ? buf[t - off] : 0.f;
        __syncthreads();
        c += add;
        buf[t] = c;
    }
    g_gbh[t] = GAMMA_N * expf(c);
}

// ---------------- main mma.sync kernel ----------------
// grid (64, 2), 256 threads (8 warps).
// GEMM1 warp tile: mW=w>>1 (m32), nW=w&1 (n32). GEMM2: mW2=w>>1 (m32), dW=w&1 (d32).
// SMEM (bytes):
//   A  [128][128] bf16 pitch 272B  : 34816
//   E  2x[64][128] bf16 pitch 272B : 34816 (stride 17408)
//   KW [128][64] bf16 pitch 144B   : 18432
//   KM 2x[64][64] bf16 pitch 144B  : 18432 (stride 9216)
//   EN 2x64 f32                    : 512   (stride 256)
//   RED 2x128 f32                  : 1024
#define SM_A    0
#define SM_E    34816
#define SM_KW   69632
#define SM_KM   88064
#define SM_EN   106496
#define SM_RED  107008
#define SM_BYTES 108032
#define PITCH_AB 272
#define PITCH_K  144
#define NTILE    64
#define NT_CTA   128

__device__ __forceinline__ void prefetch_tile(char* smem, int nb, int buf, int tid) {
    // E: 64 rows x 16 chunks
    #pragma unroll
    for (int i = 0; i < 4; ++i) {
        int f = tid + i * 256;
        int n = f >> 4, c = f & 15;
        cp_async16(smem + SM_E + buf * 17408 + n * PITCH_AB + c * 16,
                   reinterpret_cast<const char*>(g_EB) + (nb + n) * 256 + c * 16);
    }
    // KM: 64 rows(d) x 8 chunks
    #pragma unroll
    for (int i = 0; i < 2; ++i) {
        int f = tid + i * 256;
        int d = f >> 3, c = f & 7;
        cp_async16(smem + SM_KM + buf * 9216 + d * PITCH_K + c * 16,
                   reinterpret_cast<const char*>(g_KMTB) + d * (NEX * 2) + nb * 2 + c * 16);
    }
    // en: 16 chunks
    if (tid < 16)
        cp_async16(smem + SM_EN + buf * 256 + tid * 16, g_en + nb + tid * 4);
}

__global__ void __launch_bounds__(256, 1)
main_mma() {
    extern __shared__ __align__(16) char smem[];
    const int tid = threadIdx.x;
    const int w = tid >> 5, lane = tid & 31;
    const int g = lane >> 2, tg = lane & 3;
    const int mW = w >> 1;          // 0..3 (m32 tile)
    const int nW = w & 1;           // 0..1 (GEMM1 n32 / GEMM2 d32 tile)
    const int bm = blockIdx.x;
    const int split = blockIdx.y;
    const int nbase0 = split * (NEX / 2);

    // ---- prologue: A tile + tile 0 ----
    #pragma unroll
    for (int i = 0; i < 8; ++i) {
        int f = tid + i * 256;
        int m = f >> 4, c = f & 15;
        cp_async16(smem + SM_A + m * PITCH_AB + c * 16,
                   reinterpret_cast<const char*>(g_phiB) + (bm * 128 + m) * 256 + c * 16);
    }
    prefetch_tile(smem, nbase0, 0, tid);
    CP_COMMIT();

    float pnr[4];
    #pragma unroll
    for (int r = 0; r < 4; ++r) pnr[r] = g_pn[bm * 128 + mW * 32 + r * 8 + g];

    float acc2[2][4][4];   // [m16 tile i][d8 tile j][c0..c3]
    #pragma unroll
    for (int i = 0; i < 2; ++i)
        #pragma unroll
        for (int j = 0; j < 4; ++j)
            #pragma unroll
            for (int c = 0; c < 4; ++c) acc2[i][j][c] = 0.f;
    float dAcc[4] = {0.f, 0.f, 0.f, 0.f};

    for (int t = 0; t < NT_CTA; ++t) {
        const int buf = t & 1;
        CP_WAIT0();
        __syncthreads();
        if (t + 1 < NT_CTA) {
            prefetch_tile(smem, nbase0 + (t + 1) * NTILE, buf ^ 1, tid);
            CP_COMMIT();
        }

        // ---- GEMM1: S = (-2phi) . E^T  (warp m32 x n32, K=128) ----
        float acc1[2][4][4];
        #pragma unroll
        for (int i = 0; i < 2; ++i)
            #pragma unroll
            for (int j = 0; j < 4; ++j)
                #pragma unroll
                for (int c = 0; c < 4; ++c) acc1[i][j][c] = 0.f;

        const char* As = smem + SM_A + (mW * 32) * PITCH_AB;
        const char* Es = smem + SM_E + buf * 17408 + (nW * 32) * PITCH_AB;
        #pragma unroll
        for (int kk = 0; kk < 8; ++kk) {
            uint32_t a[2][4], b[4][2];
            #pragma unroll
            for (int i = 0; i < 2; ++i) {
                const char* p = As + (i * 16 + g) * PITCH_AB + kk * 32 + tg * 4;
                a[i][0] = *reinterpret_cast<const uint32_t*>(p);
                a[i][1] = *reinterpret_cast<const uint32_t*>(p + 8 * PITCH_AB);
                a[i][2] = *reinterpret_cast<const uint32_t*>(p + 16);
                a[i][3] = *reinterpret_cast<const uint32_t*>(p + 8 * PITCH_AB + 16);
            }
            #pragma unroll
            for (int j = 0; j < 4; ++j) {
                const char* p = Es + (j * 8 + g) * PITCH_AB + kk * 32 + tg * 4;
                b[j][0] = *reinterpret_cast<const uint32_t*>(p);
                b[j][1] = *reinterpret_cast<const uint32_t*>(p + 16);
            }
            #pragma unroll
            for (int i = 0; i < 2; ++i)
                #pragma unroll
                for (int j = 0; j < 4; ++j)
                    mma_bf16(acc1[i][j][0], acc1[i][j][1], acc1[i][j][2], acc1[i][j][3],
                             a[i][0], a[i][1], a[i][2], a[i][3], b[j][0], b[j][1]);
        }

        // ---- epilogue: kw = mask * exp(-d2) -> bf16 smem tile ----
        const float* enb = reinterpret_cast<const float*>(smem + SM_EN + buf * 256);
        #pragma unroll
        for (int i = 0; i < 2; ++i) {
            #pragma unroll
            for (int j = 0; j < 4; ++j) {
                const int n_loc = nW * 32 + j * 8 + 2 * tg;
                const float en0 = enb[n_loc], en1 = enb[n_loc + 1];
                const int m_loc = mW * 32 + i * 16 + g;
                // rows g (c0,c1) and g+8 (c2,c3)
                float d00 = fmaxf(pnr[i * 2 + 0] + en0 + acc1[i][j][0], 0.f);
                float d01 = fmaxf(pnr[i * 2 + 0] + en1 + acc1[i][j][1], 0.f);
                float d10 = fmaxf(pnr[i * 2 + 1] + en0 + acc1[i][j][2], 0.f);
                float d11 = fmaxf(pnr[i * 2 + 1] + en1 + acc1[i][j][3], 0.f);
                float k00 = (d00 <= 1.0f) ? __expf(-d00) : 0.f;
                float k01 = (d01 <= 1.0f) ? __expf(-d01) : 0.f;
                float k10 = (d10 <= 1.0f) ? __expf(-d10) : 0.f;
                float k11 = (d11 <= 1.0f) ? __expf(-d11) : 0.f;
                dAcc[i * 2 + 0] += k00 + k01;
                dAcc[i * 2 + 1] += k10 + k11;
                *reinterpret_cast<uint32_t*>(smem + SM_KW + m_loc * PITCH_K + n_loc * 2)
                    = pack_bf16x2(k00, k01);
                *reinterpret_cast<uint32_t*>(smem + SM_KW + (m_loc + 8) * PITCH_K + n_loc * 2)
                    = pack_bf16x2(k10, k11);
            }
        }
        __syncthreads();

        // ---- GEMM2: numer += kw . KM  (warp m32 x d32, K=64) ----
        const char* Ks = smem + SM_KW + (mW * 32) * PITCH_K;
        const char* Ms = smem + SM_KM + buf * 9216 + (nW * 32) * PITCH_K;
        #pragma unroll
        for (int kk = 0; kk < 4; ++kk) {
            uint32_t a[2][4], b[4][2];
            #pragma unroll
            for (int i = 0; i < 2; ++i) {
                const char* p = Ks + (i * 16 + g) * PITCH_K + kk * 32 + tg * 4;
                a[i][0] = *reinterpret_cast<const uint32_t*>(p);
                a[i][1] = *reinterpret_cast<const uint32_t*>(p + 8 * PITCH_K);
                a[i][2] = *reinterpret_cast<const uint32_t*>(p + 16);
                a[i][3] = *reinterpret_cast<const uint32_t*>(p + 8 * PITCH_K + 16);
            }
            #pragma unroll
            for (int j = 0; j < 4; ++j) {
                const char* p = Ms + (j * 8 + g) * PITCH_K + kk * 32 + tg * 4;
                b[j][0] = *reinterpret_cast<const uint32_t*>(p);
                b[j][1] = *reinterpret_cast<const uint32_t*>(p + 16);
            }
            #pragma unroll
            for (int i = 0; i < 2; ++i)
                #pragma unroll
                for (int j = 0; j < 4; ++j)
                    mma_bf16(acc2[i][j][0], acc2[i][j][1], acc2[i][j][2], acc2[i][j][3],
                             a[i][0], a[i][1], a[i][2], a[i][3], b[j][0], b[j][1]);
        }
    }

    // ---- write numerators ----
    #pragma unroll
    for (int i = 0; i < 2; ++i) {
        #pragma unroll
        for (int j = 0; j < 4; ++j) {
            const int m_loc = mW * 32 + i * 16 + g;
            const int d_loc = nW * 32 + j * 8 + 2 * tg;
            float* dst = g_pnum + (size_t)(split * B_N + bm * 128 + m_loc) * NDUR + d_loc;
            *reinterpret_cast<float2*>(dst) = make_float2(acc2[i][j][0], acc2[i][j][1]);
            *reinterpret_cast<float2*>(dst + 8 * NDUR) = make_float2(acc2[i][j][2], acc2[i][j][3]);
        }
    }

    // ---- denom reduce ----
    float* red = reinterpret_cast<float*>(smem + SM_RED);
    #pragma unroll
    for (int r = 0; r < 4; ++r) {
        float v = dAcc[r];
        v += __shfl_xor_sync(0xffffffffu, v, 1);
        v += __shfl_xor_sync(0xffffffffu, v, 2);
        if (tg == 0) red[nW * 128 + mW * 32 + r * 8 + g] = v;
    }
    __syncthreads();
    if (tid < 128)
        g_pden[split * B_N + bm * 128 + tid] = red[tid] + red[128 + tid];
}

// ---------------- finalize ----------------
__global__ void finalize_kernel(float* __restrict__ out) {
    const int idx = blockIdx.x * 256 + threadIdx.x;
    const int b = idx >> 6, d = idx & 63;
    float num = g_pnum[idx] + g_pnum[B_N * NDUR + idx] + g_gbh[d];
    float den = g_pden[b] + g_pden[B_N + b] + GAMMA_N + 1e-12f;
    float r = num / den;
    r = fminf(fmaxf(r, 1e-12f), 1.0f - 1e-12f);
    out[idx] = r;
}

// ---------------- launch ----------------
extern "C" void kernel_launch(void* const* d_in, const int* in_sizes, int n_in,
                              void* d_out, int out_size) {
    const float* x    = (const float*)d_in[0];
    const float* W    = (const float*)d_in[1];
    const float* bias = (const float*)d_in[2];
    const float* E    = (const float*)d_in[3];
    const float* lev  = (const float*)d_in[4];
    const float* lcen = (const float*)d_in[5];
    const float* lh   = (const float*)d_in[6];
    float* out = (float*)d_out;

    static bool attr_set = false;
    if (!attr_set) {
        cudaFuncSetAttribute(main_mma,
                             cudaFuncAttributeMaxDynamicSharedMemorySize, SM_BYTES);
        attr_set = true;
    }

    phi_pn_kernel<<<B_N / 16, 128>>>(x, W, bias);
    en_eb_kernel<<<NEX / 8, 256>>>(E);
    km_kernel<<<NEX / 4, dim3(64, 4)>>>(lev, lcen);
    bh_kernel<<<1, 64>>>(lh);
    main_mma<<<dim3(B_N / 128, 2), 256, SM_BYTES>>>();
    finalize_kernel<<<(B_N * NDUR) / 256, 256>>>(out);
}

// round 9
// speedup vs baseline: 5.0943x; 1.1044x over previous
#include <cuda_runtime.h>
#include <cuda_bf16.h>
#include <math.h>
#include <stdint.h>

#define B_N   8192
#define DIN   256
#define DE    128
#define NEX   16384
#define NDUR  64
#define GAMMA_N 3.6787944117144233e-06f   // exp(-1)/100000

// ---------------- device scratch ----------------
__device__ __align__(16) __nv_bfloat16 g_phiB[B_N * DE];   // bf16(-2*phi) [B][128]
__device__ __align__(16) __nv_bfloat16 g_EB[NEX * DE];     // bf16(E)      [NEX][128]
__device__ __align__(16) __nv_bfloat16 g_KMTB[NDUR * NEX]; // bf16(KM^T)   [64][NEX]
__device__ __align__(16) float g_pn[B_N];                  // ||phi||^2
__device__ __align__(16) float g_en[NEX];                  // ||E||^2
__device__ __align__(16) float g_gbh[NDUR];                // gamma * baseline KM
__device__ __align__(16) float g_pnum[2 * B_N * NDUR];
__device__ __align__(16) float g_pden[2 * B_N];

// ---------------- helpers ----------------
__device__ __forceinline__ void cp_async16(void* smem, const void* gmem) {
    unsigned sa = (unsigned)__cvta_generic_to_shared(smem);
    asm volatile("cp.async.cg.shared.global [%0], [%1], 16;" :: "r"(sa), "l"(gmem));
}
#define CP_COMMIT() asm volatile("cp.async.commit_group;" ::: "memory")
#define CP_WAIT0()  asm volatile("cp.async.wait_group 0;" ::: "memory")

__device__ __forceinline__ void mma_bf16(float& c0, float& c1, float& c2, float& c3,
                                         uint32_t a0, uint32_t a1, uint32_t a2, uint32_t a3,
                                         uint32_t b0, uint32_t b1) {
    asm volatile(
        "mma.sync.aligned.m16n8k16.row.col.f32.bf16.bf16.f32 "
        "{%0,%1,%2,%3}, {%4,%5,%6,%7}, {%8,%9}, {%0,%1,%2,%3};"
        : "+f"(c0), "+f"(c1), "+f"(c2), "+f"(c3)
        : "r"(a0), "r"(a1), "r"(a2), "r"(a3), "r"(b0), "r"(b1));
}
__device__ __forceinline__ uint32_t pack_bf16x2(float lo, float hi) {
    uint32_t r;
    asm("cvt.rn.bf16x2.f32 %0, %1, %2;" : "=r"(r) : "f"(hi), "f"(lo));
    return r;
}
__device__ __forceinline__ void ldmat4(uint32_t& r0, uint32_t& r1, uint32_t& r2, uint32_t& r3,
                                       uint32_t addr) {
    asm volatile("ldmatrix.sync.aligned.m8n8.x4.shared.b16 {%0,%1,%2,%3}, [%4];"
                 : "=r"(r0), "=r"(r1), "=r"(r2), "=r"(r3) : "r"(addr));
}

// ---------------- kernel 1: phi encoder -> g_phiB (bf16 -2phi), g_pn ----------------
__global__ void phi_pn_kernel(const float* __restrict__ x,
                              const float* __restrict__ W,
                              const float* __restrict__ bias) {
    __shared__ float xs[16 * DIN];
    __shared__ float pnred[16][4];
    const int tid = threadIdx.x;
    const int r0 = blockIdx.x * 16;

    const float4* xv = reinterpret_cast<const float4*>(x + r0 * DIN);
    float4* xsv = reinterpret_cast<float4*>(xs);
    #pragma unroll
    for (int i = 0; i < 8; ++i) xsv[tid + i * 128] = xv[tid + i * 128];
    const float bj = bias[tid];
    __syncthreads();

    float a[16];
    #pragma unroll
    for (int r = 0; r < 16; ++r) a[r] = 0.f;
    #pragma unroll 4
    for (int k = 0; k < DIN; ++k) {
        float w = W[k * DE + tid];
        #pragma unroll
        for (int r = 0; r < 16; ++r) a[r] += xs[r * DIN + k] * w;
    }
    #pragma unroll
    for (int r = 0; r < 16; ++r) {
        float v = a[r] + bj;
        g_phiB[(r0 + r) * DE + tid] = __float2bfloat16(-2.f * v);
        a[r] = v * v;
    }
    const int lane = tid & 31, warp = tid >> 5;
    #pragma unroll
    for (int r = 0; r < 16; ++r) {
        float v = a[r];
        #pragma unroll
        for (int o = 16; o; o >>= 1) v += __shfl_xor_sync(0xffffffffu, v, o);
        if (lane == 0) pnred[r][warp] = v;
    }
    __syncthreads();
    if (tid < 16)
        g_pn[r0 + tid] = pnred[tid][0] + pnred[tid][1] + pnred[tid][2] + pnred[tid][3];
}

// ---------------- kernel 2: en[n] = ||E_n||^2 and g_EB = bf16(E) ----------------
__global__ void en_eb_kernel(const float* __restrict__ E) {
    const int warp = threadIdx.x >> 5, lane = threadIdx.x & 31;
    const int row = blockIdx.x * 8 + warp;
    const float4* Ev = reinterpret_cast<const float4*>(E);
    float4 v = Ev[row * (DE / 4) + lane];
    uint2 pk;
    pk.x = pack_bf16x2(v.x, v.y);
    pk.y = pack_bf16x2(v.z, v.w);
    *reinterpret_cast<uint2*>(reinterpret_cast<char*>(g_EB) + row * 256 + lane * 8) = pk;
    float s = v.x * v.x + v.y * v.y + v.z * v.z + v.w * v.w;
    #pragma unroll
    for (int o = 16; o; o >>= 1) s += __shfl_xor_sync(0xffffffffu, s, o);
    if (lane == 0) g_en[row] = s;
}

// ---------------- kernel 3: KM curves -> g_KMTB bf16 [d][NEX] ----------------
__global__ void km_kernel(const float* __restrict__ lev,
                          const float* __restrict__ lcen) {
    __shared__ float buf[4][64];
    const int t = threadIdx.x, ty = threadIdx.y;
    const int row = blockIdx.x * 4 + ty;
    float ev = expf(lev[row * NDUR + t]);
    float cn = expf(lcen[row * NDUR + t]);
    float v = ev + cn;
    buf[ty][t] = v;
    #pragma unroll
    for (int off = 1; off < 64; off <<= 1) {
        __syncthreads();
        float add = (t + off < 64) ? buf[ty][t + off] : 0.f;
        __syncthreads();
        v += add;
        buf[ty][t] = v;
    }
    float at_risk = v;
    float hz = (at_risk > 0.f) ? (ev / at_risk) : 0.f;
    float lg = logf(1.f - hz + 1e-7f);
    __syncthreads();
    buf[ty][t] = lg;
    float c = lg;
    #pragma unroll
    for (int off = 1; off < 64; off <<= 1) {
        __syncthreads();
        float add = (t >= off) ? buf[ty][t - off] : 0.f;
        __syncthreads();
        c += add;
        buf[ty][t] = c;
    }
    g_KMTB[t * NEX + row] = __float2bfloat16(expf(c));
}

// ---------------- kernel 4: gamma * baseline KM ----------------
__global__ void bh_kernel(const float* __restrict__ lh) {
    __shared__ float buf[64];
    const int t = threadIdx.x;
    float h = 1.f / (1.f + expf(-lh[t]));
    float c = logf(1.f - h + 1e-7f);
    buf[t] = c;
    #pragma unroll
    for (int off = 1; off < 64; off <<= 1) {
        __syncthreads();
        float add = (t >= off) ? buf[t - off] : 0.f;
        __syncthreads();
        c += add;
        buf[t] = c;
    }
    g_gbh[t] = GAMMA_N * expf(c);
}

// ---------------- main mma.sync kernel ----------------
// grid (64, 2), 256 threads (8 warps). Warp w owns m16 rows [w*16, w*16+16).
// GEMM1: warp tile m16 x n64 (K=128). acc1 C-frags feed GEMM2 A-frags directly.
// GEMM2: warp tile m16 x d64 (K=64), kw register-resident.
// SMEM:
//   A  [128][128] bf16 pitch 272B  : 34816
//   E  2x[64][128] bf16 pitch 272B : 34816 (stride 17408)
//   KM 2x[64][64] bf16 pitch 144B  : 18432 (stride 9216)
//   EN 2x64 f32                    : 512   (stride 256)
#define SM_A    0
#define SM_E    34816
#define SM_KM   69632
#define SM_EN   88064
#define SM_BYTES 88576
#define PITCH_AB 272
#define PITCH_K  144
#define NTILE    64
#define NT_CTA   128

__device__ __forceinline__ void prefetch_tile(char* smem, int nb, int buf, int tid) {
    // E: 64 rows x 16 chunks of 16B
    #pragma unroll
    for (int i = 0; i < 4; ++i) {
        int f = tid + i * 256;
        int n = f >> 4, c = f & 15;
        cp_async16(smem + SM_E + buf * 17408 + n * PITCH_AB + c * 16,
                   reinterpret_cast<const char*>(g_EB) + (nb + n) * 256 + c * 16);
    }
    // KM: 64 rows(d) x 8 chunks
    #pragma unroll
    for (int i = 0; i < 2; ++i) {
        int f = tid + i * 256;
        int d = f >> 3, c = f & 7;
        cp_async16(smem + SM_KM + buf * 9216 + d * PITCH_K + c * 16,
                   reinterpret_cast<const char*>(g_KMTB) + d * (NEX * 2) + nb * 2 + c * 16);
    }
    if (tid < 16)
        cp_async16(smem + SM_EN + buf * 256 + tid * 16, g_en + nb + tid * 4);
}

__global__ void __launch_bounds__(256, 1)
main_mma() {
    extern __shared__ __align__(16) char smem[];
    const uint32_t sbase = (uint32_t)__cvta_generic_to_shared(smem);
    const int tid = threadIdx.x;
    const int w = tid >> 5, lane = tid & 31;
    const int g = lane >> 2, tg = lane & 3;
    const int bm = blockIdx.x;
    const int split = blockIdx.y;
    const int nbase0 = split * (NEX / 2);

    // ldmatrix lane-offset precompute
    // A (x4: m0=rows0-7 klo, m1=rows8-15 klo, m2=rows0-7 khi, m3=rows8-15 khi)
    const uint32_t a_lane = (uint32_t)((w * 16 + ((lane >> 3) & 1) * 8 + (lane & 7)) * PITCH_AB
                                       + (lane >> 4) * 16);
    // B (x4: m0=(j+0,klo), m1=(j+0,khi), m2=(j+1,klo), m3=(j+1,khi))
    const uint32_t b_laneAB = (uint32_t)(((lane >> 4) * 8 + (lane & 7)) * PITCH_AB
                                         + ((lane >> 3) & 1) * 16);
    const uint32_t b_laneK  = (uint32_t)(((lane >> 4) * 8 + (lane & 7)) * PITCH_K
                                         + ((lane >> 3) & 1) * 16);

    // ---- prologue: A tile + tile 0 ----
    #pragma unroll
    for (int i = 0; i < 8; ++i) {
        int f = tid + i * 256;
        int m = f >> 4, c = f & 15;
        cp_async16(smem + SM_A + m * PITCH_AB + c * 16,
                   reinterpret_cast<const char*>(g_phiB) + (bm * 128 + m) * 256 + c * 16);
    }
    prefetch_tile(smem, nbase0, 0, tid);
    CP_COMMIT();

    const float pnr0 = g_pn[bm * 128 + w * 16 + g];
    const float pnr1 = g_pn[bm * 128 + w * 16 + g + 8];

    float acc2[8][4];
    #pragma unroll
    for (int j = 0; j < 8; ++j)
        #pragma unroll
        for (int c = 0; c < 4; ++c) acc2[j][c] = 0.f;
    float dAcc0 = 0.f, dAcc1 = 0.f;

    for (int t = 0; t < NT_CTA; ++t) {
        const int buf = t & 1;
        CP_WAIT0();
        __syncthreads();
        if (t + 1 < NT_CTA) {
            prefetch_tile(smem, nbase0 + (t + 1) * NTILE, buf ^ 1, tid);
            CP_COMMIT();
        }

        // ---- GEMM1: S = (-2phi) . E^T  (m16 x n64, K=128) ----
        float acc1[8][4];
        #pragma unroll
        for (int j = 0; j < 8; ++j)
            #pragma unroll
            for (int c = 0; c < 4; ++c) acc1[j][c] = 0.f;

        const uint32_t EsB = sbase + SM_E + buf * 17408 + b_laneAB;
        const uint32_t AsB = sbase + SM_A + a_lane;
        #pragma unroll
        for (int kk = 0; kk < 8; ++kk) {
            uint32_t a0, a1, a2, a3;
            ldmat4(a0, a1, a2, a3, AsB + kk * 32);
            uint32_t b[8][2];
            #pragma unroll
            for (int bj = 0; bj < 4; ++bj)
                ldmat4(b[2 * bj][0], b[2 * bj][1], b[2 * bj + 1][0], b[2 * bj + 1][1],
                       EsB + bj * 16 * PITCH_AB + kk * 32);
            #pragma unroll
            for (int j = 0; j < 8; ++j)
                mma_bf16(acc1[j][0], acc1[j][1], acc1[j][2], acc1[j][3],
                         a0, a1, a2, a3, b[j][0], b[j][1]);
        }

        // ---- epilogue: kw = mask * exp(-d2), kept in registers as GEMM2 A-frags ----
        uint32_t kwreg[8][2];
        const float* enb = reinterpret_cast<const float*>(smem + SM_EN + buf * 256);
        #pragma unroll
        for (int j = 0; j < 8; ++j) {
            float2 en2 = *reinterpret_cast<const float2*>(enb + j * 8 + 2 * tg);
            float d00 = fmaxf(pnr0 + en2.x + acc1[j][0], 0.f);
            float d01 = fmaxf(pnr0 + en2.y + acc1[j][1], 0.f);
            float d10 = fmaxf(pnr1 + en2.x + acc1[j][2], 0.f);
            float d11 = fmaxf(pnr1 + en2.y + acc1[j][3], 0.f);
            float k00 = (d00 <= 1.0f) ? __expf(-d00) : 0.f;
            float k01 = (d01 <= 1.0f) ? __expf(-d01) : 0.f;
            float k10 = (d10 <= 1.0f) ? __expf(-d10) : 0.f;
            float k11 = (d11 <= 1.0f) ? __expf(-d11) : 0.f;
            dAcc0 += k00 + k01;
            dAcc1 += k10 + k11;
            kwreg[j][0] = pack_bf16x2(k00, k01);
            kwreg[j][1] = pack_bf16x2(k10, k11);
        }

        // ---- GEMM2: numer += kw . KM  (m16 x d64, K=64) ----
        const uint32_t MsB = sbase + SM_KM + buf * 9216 + b_laneK;
        #pragma unroll
        for (int kk = 0; kk < 4; ++kk) {
            uint32_t b[8][2];
            #pragma unroll
            for (int bj = 0; bj < 4; ++bj)
                ldmat4(b[2 * bj][0], b[2 * bj][1], b[2 * bj + 1][0], b[2 * bj + 1][1],
                       MsB + bj * 16 * PITCH_K + kk * 32);
            const uint32_t a0 = kwreg[2 * kk][0], a1 = kwreg[2 * kk][1];
            const uint32_t a2 = kwreg[2 * kk + 1][0], a3 = kwreg[2 * kk + 1][1];
            #pragma unroll
            for (int j = 0; j < 8; ++j)
                mma_bf16(acc2[j][0], acc2[j][1], acc2[j][2], acc2[j][3],
                         a0, a1, a2, a3, b[j][0], b[j][1]);
        }
    }

    // ---- write numerators ----
    #pragma unroll
    for (int j = 0; j < 8; ++j) {
        const int m_loc = w * 16 + g;
        const int d_loc = j * 8 + 2 * tg;
        float* dst = g_pnum + (size_t)(split * B_N + bm * 128 + m_loc) * NDUR + d_loc;
        *reinterpret_cast<float2*>(dst) = make_float2(acc2[j][0], acc2[j][1]);
        *reinterpret_cast<float2*>(dst + 8 * NDUR) = make_float2(acc2[j][2], acc2[j][3]);
    }

    // ---- denom: quad reduce, each m-row owned by exactly one warp ----
    dAcc0 += __shfl_xor_sync(0xffffffffu, dAcc0, 1);
    dAcc0 += __shfl_xor_sync(0xffffffffu, dAcc0, 2);
    dAcc1 += __shfl_xor_sync(0xffffffffu, dAcc1, 1);
    dAcc1 += __shfl_xor_sync(0xffffffffu, dAcc1, 2);
    if (tg == 0) {
        g_pden[split * B_N + bm * 128 + w * 16 + g] = dAcc0;
        g_pden[split * B_N + bm * 128 + w * 16 + g + 8] = dAcc1;
    }
}

// ---------------- finalize ----------------
__global__ void finalize_kernel(float* __restrict__ out) {
    const int idx = blockIdx.x * 256 + threadIdx.x;
    const int b = idx >> 6, d = idx & 63;
    float num = g_pnum[idx] + g_pnum[B_N * NDUR + idx] + g_gbh[d];
    float den = g_pden[b] + g_pden[B_N + b] + GAMMA_N + 1e-12f;
    float r = num / den;
    r = fminf(fmaxf(r, 1e-12f), 1.0f - 1e-12f);
    out[idx] = r;
}

// ---------------- launch ----------------
extern "C" void kernel_launch(void* const* d_in, const int* in_sizes, int n_in,
                              void* d_out, int out_size) {
    const float* x    = (const float*)d_in[0];
    const float* W    = (const float*)d_in[1];
    const float* bias = (const float*)d_in[2];
    const float* E    = (const float*)d_in[3];
    const float* lev  = (const float*)d_in[4];
    const float* lcen = (const float*)d_in[5];
    const float* lh   = (const float*)d_in[6];
    float* out = (float*)d_out;

    static bool attr_set = false;
    if (!attr_set) {
        cudaFuncSetAttribute(main_mma,
                             cudaFuncAttributeMaxDynamicSharedMemorySize, SM_BYTES);
        attr_set = true;
    }

    phi_pn_kernel<<<B_N / 16, 128>>>(x, W, bias);
    en_eb_kernel<<<NEX / 8, 256>>>(E);
    km_kernel<<<NEX / 4, dim3(64, 4)>>>(lev, lcen);
    bh_kernel<<<1, 64>>>(lh);
    main_mma<<<dim3(B_N / 128, 2), 256, SM_BYTES>>>();
    finalize_kernel<<<(B_N * NDUR) / 256, 256>>>(out);
}

// round 11
// speedup vs baseline: 5.8509x; 1.1485x over previous
#include <cuda_runtime.h>
#include <cuda_bf16.h>
#include <math.h>
#include <stdint.h>

#define B_N   8192
#define DIN   256
#define DE    128
#define NEX   16384
#define NDUR  64
#define NSPLIT 4
#define GAMMA_N 3.6787944117144233e-06f   // exp(-1)/100000

// ---------------- device scratch ----------------
__device__ __align__(16) __nv_bfloat16 g_phiB[B_N * DE];   // bf16(-2*phi) [B][128]
__device__ __align__(16) __nv_bfloat16 g_EB[NEX * DE];     // bf16(E)      [NEX][128]
__device__ __align__(16) __nv_bfloat16 g_KMTB[NDUR * NEX]; // bf16(KM^T)   [64][NEX]
__device__ __align__(16) float g_pn[B_N];                  // ||phi||^2
__device__ __align__(16) float g_en[NEX];                  // ||E||^2
__device__ __align__(16) float g_gbh[NDUR];                // gamma * baseline KM
__device__ __align__(16) float g_pnum[NSPLIT * B_N * NDUR];
__device__ __align__(16) float g_pden[NSPLIT * B_N];

// ---------------- helpers ----------------
__device__ __forceinline__ void cp_async16(void* smem, const void* gmem) {
    unsigned sa = (unsigned)__cvta_generic_to_shared(smem);
    asm volatile("cp.async.cg.shared.global [%0], [%1], 16;" :: "r"(sa), "l"(gmem));
}
#define CP_COMMIT() asm volatile("cp.async.commit_group;" ::: "memory")
#define CP_WAIT0()  asm volatile("cp.async.wait_group 0;" ::: "memory")

__device__ __forceinline__ void mma_bf16(float& c0, float& c1, float& c2, float& c3,
                                         uint32_t a0, uint32_t a1, uint32_t a2, uint32_t a3,
                                         uint32_t b0, uint32_t b1) {
    asm volatile(
        "mma.sync.aligned.m16n8k16.row.col.f32.bf16.bf16.f32 "
        "{%0,%1,%2,%3}, {%4,%5,%6,%7}, {%8,%9}, {%0,%1,%2,%3};"
        : "+f"(c0), "+f"(c1), "+f"(c2), "+f"(c3)
        : "r"(a0), "r"(a1), "r"(a2), "r"(a3), "r"(b0), "r"(b1));
}
__device__ __forceinline__ uint32_t pack_bf16x2(float lo, float hi) {
    uint32_t r;
    asm("cvt.rn.bf16x2.f32 %0, %1, %2;" : "=r"(r) : "f"(hi), "f"(lo));
    return r;
}
__device__ __forceinline__ void ldmat4(uint32_t& r0, uint32_t& r1, uint32_t& r2, uint32_t& r3,
                                       uint32_t addr) {
    asm volatile("ldmatrix.sync.aligned.m8n8.x4.shared.b16 {%0,%1,%2,%3}, [%4];"
                 : "=r"(r0), "=r"(r1), "=r"(r2), "=r"(r3) : "r"(addr));
}

// ---------------- kernel 1: phi encoder -> g_phiB (bf16 -2phi), g_pn ----------------
__global__ void phi_pn_kernel(const float* __restrict__ x,
                              const float* __restrict__ W,
                              const float* __restrict__ bias) {
    __shared__ float xs[16 * DIN];
    __shared__ float pnred[16][4];
    const int tid = threadIdx.x;
    const int r0 = blockIdx.x * 16;

    const float4* xv = reinterpret_cast<const float4*>(x + r0 * DIN);
    float4* xsv = reinterpret_cast<float4*>(xs);
    #pragma unroll
    for (int i = 0; i < 8; ++i) xsv[tid + i * 128] = xv[tid + i * 128];
    const float bj = bias[tid];
    __syncthreads();

    float a[16];
    #pragma unroll
    for (int r = 0; r < 16; ++r) a[r] = 0.f;
    #pragma unroll 4
    for (int k = 0; k < DIN; ++k) {
        float w = W[k * DE + tid];
        #pragma unroll
        for (int r = 0; r < 16; ++r) a[r] += xs[r * DIN + k] * w;
    }
    #pragma unroll
    for (int r = 0; r < 16; ++r) {
        float v = a[r] + bj;
        g_phiB[(r0 + r) * DE + tid] = __float2bfloat16(-2.f * v);
        a[r] = v * v;
    }
    const int lane = tid & 31, warp = tid >> 5;
    #pragma unroll
    for (int r = 0; r < 16; ++r) {
        float v = a[r];
        #pragma unroll
        for (int o = 16; o; o >>= 1) v += __shfl_xor_sync(0xffffffffu, v, o);
        if (lane == 0) pnred[r][warp] = v;
    }
    __syncthreads();
    if (tid < 16)
        g_pn[r0 + tid] = pnred[tid][0] + pnred[tid][1] + pnred[tid][2] + pnred[tid][3];
}

// ---------------- kernel 2: en[n] = ||E_n||^2 and g_EB = bf16(E) ----------------
__global__ void en_eb_kernel(const float* __restrict__ E) {
    const int warp = threadIdx.x >> 5, lane = threadIdx.x & 31;
    const int row = blockIdx.x * 8 + warp;
    const float4* Ev = reinterpret_cast<const float4*>(E);
    float4 v = Ev[row * (DE / 4) + lane];
    uint2 pk;
    pk.x = pack_bf16x2(v.x, v.y);
    pk.y = pack_bf16x2(v.z, v.w);
    *reinterpret_cast<uint2*>(reinterpret_cast<char*>(g_EB) + row * 256 + lane * 8) = pk;
    float s = v.x * v.x + v.y * v.y + v.z * v.z + v.w * v.w;
    #pragma unroll
    for (int o = 16; o; o >>= 1) s += __shfl_xor_sync(0xffffffffu, s, o);
    if (lane == 0) g_en[row] = s;
}

// ---------------- kernel 3: KM curves -> g_KMTB bf16 [d][NEX] ----------------
__global__ void km_kernel(const float* __restrict__ lev,
                          const float* __restrict__ lcen) {
    __shared__ float buf[4][64];
    const int t = threadIdx.x, ty = threadIdx.y;
    const int row = blockIdx.x * 4 + ty;
    float ev = expf(lev[row * NDUR + t]);
    float cn = expf(lcen[row * NDUR + t]);
    float v = ev + cn;
    buf[ty][t] = v;
    #pragma unroll
    for (int off = 1; off < 64; off <<= 1) {
        __syncthreads();
        float add = (t + off < 64) ? buf[ty][t + off] : 0.f;
        __syncthreads();
        v += add;
        buf[ty][t] = v;
    }
    float at_risk = v;
    float hz = (at_risk > 0.f) ? (ev / at_risk) : 0.f;
    float lg = logf(1.f - hz + 1e-7f);
    __syncthreads();
    buf[ty][t] = lg;
    float c = lg;
    #pragma unroll
    for (int off = 1; off < 64; off <<= 1) {
        __syncthreads();
        float add = (t >= off) ? buf[ty][t - off] : 0.f;
        __syncthreads();
        c += add;
        buf[ty][t] = c;
    }
    g_KMTB[t * NEX + row] = __float2bfloat16(expf(c));
}

// ---------------- kernel 4: gamma * baseline KM ----------------
__global__ void bh_kernel(const float* __restrict__ lh) {
    __shared__ float buf[64];
    const int t = threadIdx.x;
    float h = 1.f / (1.f + expf(-lh[t]));
    float c = logf(1.f - h + 1e-7f);
    buf[t] = c;
    #pragma unroll
    for (int off = 1; off < 64; off <<= 1) {
        __syncthreads();
        float add = (t >= off) ? buf[t - off] : 0.f;
        __syncthreads();
        c += add;
        buf[t] = c;
    }
    g_gbh[t] = GAMMA_N * expf(c);
}

// ---------------- main mma.sync kernel ----------------
// grid (64, 4), 256 threads (8 warps), 2 CTAs/SM (4 warps per SMSP).
// Warp w owns m16 rows [w*16, w*16+16).
// GEMM1: warp tile m16 x n64 (K=128). acc1 C-frags feed GEMM2 A-frags directly.
// GEMM2: warp tile m16 x d64 (K=64), kw register-resident.
#define SM_A    0
#define SM_E    34816
#define SM_KM   69632
#define SM_EN   88064
#define SM_BYTES 88576
#define PITCH_AB 272
#define PITCH_K  144
#define NTILE    64
#define NT_CTA   (NEX / NSPLIT / NTILE)   // 64

__device__ __forceinline__ void prefetch_tile(char* smem, int nb, int buf, int tid) {
    // E: 64 rows x 16 chunks of 16B
    #pragma unroll
    for (int i = 0; i < 4; ++i) {
        int f = tid + i * 256;
        int n = f >> 4, c = f & 15;
        cp_async16(smem + SM_E + buf * 17408 + n * PITCH_AB + c * 16,
                   reinterpret_cast<const char*>(g_EB) + (nb + n) * 256 + c * 16);
    }
    // KM: 64 rows(d) x 8 chunks
    #pragma unroll
    for (int i = 0; i < 2; ++i) {
        int f = tid + i * 256;
        int d = f >> 3, c = f & 7;
        cp_async16(smem + SM_KM + buf * 9216 + d * PITCH_K + c * 16,
                   reinterpret_cast<const char*>(g_KMTB) + d * (NEX * 2) + nb * 2 + c * 16);
    }
    if (tid < 16)
        cp_async16(smem + SM_EN + buf * 256 + tid * 16, g_en + nb + tid * 4);
}

__global__ void __launch_bounds__(256, 2)
main_mma() {
    extern __shared__ __align__(16) char smem[];
    const uint32_t sbase = (uint32_t)__cvta_generic_to_shared(smem);
    const int tid = threadIdx.x;
    const int w = tid >> 5, lane = tid & 31;
    const int g = lane >> 2, tg = lane & 3;
    const int bm = blockIdx.x;
    const int split = blockIdx.y;
    const int nbase0 = split * (NEX / NSPLIT);

    // ldmatrix lane-offset precompute
    const uint32_t a_lane = (uint32_t)((w * 16 + ((lane >> 3) & 1) * 8 + (lane & 7)) * PITCH_AB
                                       + (lane >> 4) * 16);
    const uint32_t b_laneAB = (uint32_t)(((lane >> 4) * 8 + (lane & 7)) * PITCH_AB
                                         + ((lane >> 3) & 1) * 16);
    const uint32_t b_laneK  = (uint32_t)(((lane >> 4) * 8 + (lane & 7)) * PITCH_K
                                         + ((lane >> 3) & 1) * 16);

    // ---- prologue: A tile + tile 0 ----
    #pragma unroll
    for (int i = 0; i < 8; ++i) {
        int f = tid + i * 256;
        int m = f >> 4, c = f & 15;
        cp_async16(smem + SM_A + m * PITCH_AB + c * 16,
                   reinterpret_cast<const char*>(g_phiB) + (bm * 128 + m) * 256 + c * 16);
    }
    prefetch_tile(smem, nbase0, 0, tid);
    CP_COMMIT();

    const float pnr0 = g_pn[bm * 128 + w * 16 + g];
    const float pnr1 = g_pn[bm * 128 + w * 16 + g + 8];

    float acc2[8][4];
    #pragma unroll
    for (int j = 0; j < 8; ++j)
        #pragma unroll
        for (int c = 0; c < 4; ++c) acc2[j][c] = 0.f;
    float dAcc0 = 0.f, dAcc1 = 0.f;

    for (int t = 0; t < NT_CTA; ++t) {
        const int buf = t & 1;
        CP_WAIT0();
        __syncthreads();
        if (t + 1 < NT_CTA) {
            prefetch_tile(smem, nbase0 + (t + 1) * NTILE, buf ^ 1, tid);
            CP_COMMIT();
        }

        // ---- GEMM1: S = (-2phi) . E^T  (m16 x n64, K=128) ----
        float acc1[8][4];
        #pragma unroll
        for (int j = 0; j < 8; ++j)
            #pragma unroll
            for (int c = 0; c < 4; ++c) acc1[j][c] = 0.f;

        const uint32_t EsB = sbase + SM_E + buf * 17408 + b_laneAB;
        const uint32_t AsB = sbase + SM_A + a_lane;
        #pragma unroll
        for (int kk = 0; kk < 8; ++kk) {
            uint32_t a0, a1, a2, a3;
            ldmat4(a0, a1, a2, a3, AsB + kk * 32);
            uint32_t b[8][2];
            #pragma unroll
            for (int bj = 0; bj < 4; ++bj)
                ldmat4(b[2 * bj][0], b[2 * bj][1], b[2 * bj + 1][0], b[2 * bj + 1][1],
                       EsB + bj * 16 * PITCH_AB + kk * 32);
            #pragma unroll
            for (int j = 0; j < 8; ++j)
                mma_bf16(acc1[j][0], acc1[j][1], acc1[j][2], acc1[j][3],
                         a0, a1, a2, a3, b[j][0], b[j][1]);
        }

        // ---- epilogue: kw = mask * exp(-d2), kept in registers as GEMM2 A-frags ----
        uint32_t kwreg[8][2];
        const float* enb = reinterpret_cast<const float*>(smem + SM_EN + buf * 256);
        #pragma unroll
        for (int j = 0; j < 8; ++j) {
            float2 en2 = *reinterpret_cast<const float2*>(enb + j * 8 + 2 * tg);
            float d00 = fmaxf(pnr0 + en2.x + acc1[j][0], 0.f);
            float d01 = fmaxf(pnr0 + en2.y + acc1[j][1], 0.f);
            float d10 = fmaxf(pnr1 + en2.x + acc1[j][2], 0.f);
            float d11 = fmaxf(pnr1 + en2.y + acc1[j][3], 0.f);
            float k00 = (d00 <= 1.0f) ? __expf(-d00) : 0.f;
            float k01 = (d01 <= 1.0f) ? __expf(-d01) : 0.f;
            float k10 = (d10 <= 1.0f) ? __expf(-d10) : 0.f;
            float k11 = (d11 <= 1.0f) ? __expf(-d11) : 0.f;
            dAcc0 += k00 + k01;
            dAcc1 += k10 + k11;
            kwreg[j][0] = pack_bf16x2(k00, k01);
            kwreg[j][1] = pack_bf16x2(k10, k11);
        }

        // ---- GEMM2: numer += kw . KM  (m16 x d64, K=64) ----
        const uint32_t MsB = sbase + SM_KM + buf * 9216 + b_laneK;
        #pragma unroll
        for (int kk = 0; kk < 4; ++kk) {
            uint32_t b[8][2];
            #pragma unroll
            for (int bj = 0; bj < 4; ++bj)
                ldmat4(b[2 * bj][0], b[2 * bj][1], b[2 * bj + 1][0], b[2 * bj + 1][1],
                       MsB + bj * 16 * PITCH_K + kk * 32);
            const uint32_t a0 = kwreg[2 * kk][0], a1 = kwreg[2 * kk][1];
            const uint32_t a2 = kwreg[2 * kk + 1][0], a3 = kwreg[2 * kk + 1][1];
            #pragma unroll
            for (int j = 0; j < 8; ++j)
                mma_bf16(acc2[j][0], acc2[j][1], acc2[j][2], acc2[j][3],
                         a0, a1, a2, a3, b[j][0], b[j][1]);
        }
    }

    // ---- write numerators ----
    #pragma unroll
    for (int j = 0; j < 8; ++j) {
        const int m_loc = w * 16 + g;
        const int d_loc = j * 8 + 2 * tg;
        float* dst = g_pnum + (size_t)(split * B_N + bm * 128 + m_loc) * NDUR + d_loc;
        *reinterpret_cast<float2*>(dst) = make_float2(acc2[j][0], acc2[j][1]);
        *reinterpret_cast<float2*>(dst + 8 * NDUR) = make_float2(acc2[j][2], acc2[j][3]);
    }

    // ---- denom: quad reduce, each m-row owned by exactly one warp ----
    dAcc0 += __shfl_xor_sync(0xffffffffu, dAcc0, 1);
    dAcc0 += __shfl_xor_sync(0xffffffffu, dAcc0, 2);
    dAcc1 += __shfl_xor_sync(0xffffffffu, dAcc1, 1);
    dAcc1 += __shfl_xor_sync(0xffffffffu, dAcc1, 2);
    if (tg == 0) {
        g_pden[split * B_N + bm * 128 + w * 16 + g] = dAcc0;
        g_pden[split * B_N + bm * 128 + w * 16 + g + 8] = dAcc1;
    }
}

// ---------------- finalize ----------------
__global__ void finalize_kernel(float* __restrict__ out) {
    const int idx = blockIdx.x * 256 + threadIdx.x;
    const int b = idx >> 6, d = idx & 63;
    float num = g_gbh[d];
    float den = GAMMA_N + 1e-12f;
    #pragma unroll
    for (int s = 0; s < NSPLIT; ++s) {
        num += g_pnum[s * B_N * NDUR + idx];
        den += g_pden[s * B_N + b];
    }
    float r = num / den;
    r = fminf(fmaxf(r, 1e-12f), 1.0f - 1e-12f);
    out[idx] = r;
}

// ---------------- launch ----------------
extern "C" void kernel_launch(void* const* d_in, const int* in_sizes, int n_in,
                              void* d_out, int out_size) {
    const float* x    = (const float*)d_in[0];
    const float* W    = (const float*)d_in[1];
    const float* bias = (const float*)d_in[2];
    const float* E    = (const float*)d_in[3];
    const float* lev  = (const float*)d_in[4];
    const float* lcen = (const float*)d_in[5];
    const float* lh   = (const float*)d_in[6];
    float* out = (float*)d_out;

    static bool attr_set = false;
    if (!attr_set) {
        cudaFuncSetAttribute(main_mma,
                             cudaFuncAttributeMaxDynamicSharedMemorySize, SM_BYTES);
        attr_set = true;
    }

    phi_pn_kernel<<<B_N / 16, 128>>>(x, W, bias);
    en_eb_kernel<<<NEX / 8, 256>>>(E);
    km_kernel<<<NEX / 4, dim3(64, 4)>>>(lev, lcen);
    bh_kernel<<<1, 64>>>(lh);
    main_mma<<<dim3(B_N / 128, NSPLIT), 256, SM_BYTES>>>();
    finalize_kernel<<<(B_N * NDUR) / 256, 256>>>(out);
}